// round 15
// baseline (speedup 1.0000x reference)
#include <cuda_runtime.h>
#include <cuda_bf16.h>
#include <cstdint>

#define NB  16
#define NC  512
#define NHW 4096
#define NIP 10

// ---------------- scratch (static device globals; no allocations) ----------------
__device__ __align__(16) __nv_bfloat16 g_xh[NB*NC*NHW];    // bf16 copy of x (64MB)
__device__ __align__(16) __nv_bfloat16 g_WhA[NB*NC*NC];    // split-K half 0, bf16 (8MB)
__device__ __align__(16) __nv_bfloat16 g_WhB[NB*NC*NC];    // split-K half 1, bf16 (8MB)
__device__ float g_Ws[NB*NC*NC];                           // Gram f32 (16MB)
__device__ float g_v  [NB*NC];        // v after 10 power iterations (unit)
__device__ float g_u  [NB*NHW];       // unnormalized u = X^T v
__device__ float g_upar[NB*16*NHW];   // c-chunk partials of u (4MB)
__device__ float g_uinv [NB];         // 1/||u||

// ================= PTX helpers =================
__device__ __forceinline__ uint32_t smem_u32(const void* p) {
    uint32_t a;
    asm("{ .reg .u64 t; cvta.to.shared.u64 t, %1; cvt.u32.u64 %0, t; }" : "=r"(a) : "l"(p));
    return a;
}
__device__ __forceinline__ void cp16(uint32_t dst, const void* gsrc) {
    asm volatile("cp.async.cg.shared.global [%0], [%1], 16;"
                 :: "r"(dst), "l"(__cvta_generic_to_global(gsrc)) : "memory");
}
#define CP_COMMIT() asm volatile("cp.async.commit_group;" ::: "memory")

__device__ __forceinline__ void ldsm4(uint32_t* r, uint32_t addr) {
    asm volatile("ldmatrix.sync.aligned.m8n8.x4.shared.b16 {%0,%1,%2,%3}, [%4];"
        : "=r"(r[0]), "=r"(r[1]), "=r"(r[2]), "=r"(r[3]) : "r"(addr));
}
__device__ __forceinline__ void mma16816(float* d, const uint32_t* a, uint32_t b0, uint32_t b1) {
    asm volatile("mma.sync.aligned.m16n8k16.row.col.f32.bf16.bf16.f32 "
        "{%0,%1,%2,%3}, {%4,%5,%6,%7}, {%8,%9}, {%0,%1,%2,%3};"
        : "+f"(d[0]), "+f"(d[1]), "+f"(d[2]), "+f"(d[3])
        : "r"(a[0]), "r"(a[1]), "r"(a[2]), "r"(a[3]), "r"(b0), "r"(b1));
}
__device__ __forceinline__ float bflo(uint32_t p) { return __uint_as_float(p << 16); }
__device__ __forceinline__ float bfhi(uint32_t p) { return __uint_as_float(p & 0xffff0000u); }

// =====================================================================
// Kernel 0: convert x (f32) -> g_xh (bf16). Single launch.
// =====================================================================
__global__ __launch_bounds__(256)
void conv_kernel(const float* __restrict__ x) {
    const size_t i = (size_t)blockIdx.x * 256 + threadIdx.x;  // float4 idx
    const float4 v = ((const float4*)x)[i];
    union { struct { __nv_bfloat162 a, b; } h; uint2 u; } cv;
    cv.h.a = __floats2bfloat162_rn(v.x, v.y);
    cv.h.b = __floats2bfloat162_rn(v.z, v.w);
    ((uint2*)g_xh)[i] = cv.u;
}

// =====================================================================
// Kernel 1: Gram via bf16 mma.sync (R13-proven core). CTA tile 64x128,
// 256 thr = 8 warps (2m x 4n of 32x32), __launch_bounds__(256,3).
// Symmetric decomposition (mi in 0..7, nj in 0..3): tiles with mi >= 2nj.
// Straddle tiles alias A into B smem. Split-K=2, BK=32, 4-stage cp.async,
// prefetch +2, one barrier per chunk. Epilogue writes bf16 halves.
// =====================================================================
#define BK 32
#define A_BYTES (64 * 80)             // 5120
#define B_BYTES (128 * 80)            // 10240
#define STAGE_BYTES (A_BYTES + B_BYTES)  // 15360
#define GRAM_SMEM (4 * STAGE_BYTES)   // 61440 >= epilogue 64*129*4 (33024)

__global__ __launch_bounds__(256, 3)
void gram_mma(void) {
    extern __shared__ char ds[];
    const uint32_t sb = smem_u32(ds);
    const int tid = threadIdx.x;
    const int wid = tid >> 5, lane = tid & 31;

    const int b = blockIdx.y;
    const int z = blockIdx.z;            // split-K half
    int nj = 0, r = blockIdx.x;
    while (r >= 8 - 2 * nj) { r -= 8 - 2 * nj; nj++; }
    const int mi = 2 * nj + r;
    const int i0 = mi * 64, j0 = nj * 128;
    const bool straddle = (mi == 2 * nj) || (mi == 2 * nj + 1);
    const bool dotrans  = (mi >= 2 * nj + 2);
    const int kbase = z * 2048;

    const __nv_bfloat16* __restrict__ Xb = g_xh + (size_t)b * NC * NHW;
    __nv_bfloat16* __restrict__ Whz = (z ? g_WhB : g_WhA) + (size_t)b * NC * NC;

    // loader: B = 2 cp16/thread (128 rows x 4 qcols), A = 1 cp16/thread (64 x 4)
    const int br0 = tid >> 2,          bq0 = tid & 3;
    const int br1 = (tid + 256) >> 2,  bq1 = tid & 3;
    const int arow = tid >> 2,         akq = tid & 3;

    auto load_chunk = [&](int c) {
        const uint32_t stg = sb + (uint32_t)(c & 3) * STAGE_BYTES;
        const uint32_t bbs = stg + A_BYTES;
        const __nv_bfloat16* gB = Xb + (size_t)j0 * NHW + kbase + c * BK;
        cp16(bbs + br0 * 80 + bq0 * 16, gB + (size_t)br0 * NHW + bq0 * 8);
        cp16(bbs + br1 * 80 + bq1 * 16, gB + (size_t)br1 * NHW + bq1 * 8);
        if (!straddle) {
            const __nv_bfloat16* gA = Xb + (size_t)i0 * NHW + kbase + c * BK;
            cp16(stg + arow * 80 + akq * 16, gA + (size_t)arow * NHW + akq * 8);
        }
        CP_COMMIT();
    };

    load_chunk(0); load_chunk(1);

    // per-lane ldmatrix address offsets (bytes) — verified R5..R14
    const uint32_t aoff = (uint32_t)((lane & 15) * 80 + (lane >> 4) * 16);
    const uint32_t boff = (uint32_t)(((lane & 7) | (((lane >> 4) & 1) << 3)) * 80
                                     + ((lane >> 3) & 1) * 16);
    const uint32_t wmB = (uint32_t)((wid & 1) * 32) * 80;   // warp m0 byte off
    const uint32_t wnB = (uint32_t)((wid >> 1) * 32) * 80;  // warp n0 byte off
    const uint32_t astrad = (uint32_t)(mi & 1) * 5120u;     // A offset inside B tile

    float acc[2][4][4];
    #pragma unroll
    for (int mt = 0; mt < 2; mt++)
        #pragma unroll
        for (int nt = 0; nt < 4; nt++)
            #pragma unroll
            for (int q = 0; q < 4; q++) acc[mt][nt][q] = 0.f;

    for (int c = 0; c < 64; c++) {
        if (c < 63) asm volatile("cp.async.wait_group 1;" ::: "memory");
        else        asm volatile("cp.async.wait_group 0;" ::: "memory");
        __syncthreads();     // chunk c resident; stage (c+2)%4 reads (chunk c-2) done

        if (c + 2 < 64) load_chunk(c + 2);

        const uint32_t stg = sb + (uint32_t)(c & 3) * STAGE_BYTES;
        const uint32_t bbs = stg + A_BYTES;
        const uint32_t abs_ = straddle ? (bbs + astrad) : stg;

        #pragma unroll
        for (int ks = 0; ks < 2; ks++) {
            uint32_t af[2][4], bf[2][4];
            #pragma unroll
            for (int mt = 0; mt < 2; mt++)
                ldsm4(af[mt], abs_ + wmB + (uint32_t)(mt * 1280 + ks * 32) + aoff);
            #pragma unroll
            for (int nh = 0; nh < 2; nh++)
                ldsm4(bf[nh], bbs + wnB + (uint32_t)(nh * 1280 + ks * 32) + boff);
            #pragma unroll
            for (int mt = 0; mt < 2; mt++)
                #pragma unroll
                for (int nt = 0; nt < 4; nt++)
                    mma16816(acc[mt][nt], af[mt], bf[nt >> 1][2 * (nt & 1)],
                             bf[nt >> 1][2 * (nt & 1) + 1]);
        }
    }
    __syncthreads();   // all MMA reads done before smem reuse

    // ---- epilogue: stage 64x128 C in smem (stride 129 floats) ----
    float* st = (float*)ds;
    {
        const int gid = lane >> 2, tig = lane & 3;
        const int wm0 = (wid & 1) * 32, wn0 = (wid >> 1) * 32;
        #pragma unroll
        for (int mt = 0; mt < 2; mt++)
            #pragma unroll
            for (int nt = 0; nt < 4; nt++) {
                const int m = wm0 + mt * 16 + gid;
                const int n = wn0 + nt * 8 + tig * 2;
                st[m * 129 + n]           = acc[mt][nt][0];
                st[m * 129 + n + 1]       = acc[mt][nt][1];
                st[(m + 8) * 129 + n]     = acc[mt][nt][2];
                st[(m + 8) * 129 + n + 1] = acc[mt][nt][3];
            }
    }
    __syncthreads();

    // direct block (i0, j0): 64 x 128, bf16
    #pragma unroll
    for (int it = 0; it < 8; it++) {
        const int e = it * 256 + tid;        // 2048 uint2 (4 cols each)
        const int row = e >> 5, n = (e & 31) * 4;
        union { struct { __nv_bfloat162 a, b; } h; uint2 u; } cv;
        cv.h.a = __floats2bfloat162_rn(st[row * 129 + n],     st[row * 129 + n + 1]);
        cv.h.b = __floats2bfloat162_rn(st[row * 129 + n + 2], st[row * 129 + n + 3]);
        *(uint2*)&Whz[(size_t)(i0 + row) * NC + j0 + n] = cv.u;
    }
    // transposed block (j0, i0): 128 x 64, bf16
    if (dotrans) {
        #pragma unroll
        for (int it = 0; it < 8; it++) {
            const int e = it * 256 + tid;    // 2048 uint2
            const int n = e >> 4, m = (e & 15) * 4;
            union { struct { __nv_bfloat162 a, b; } h; uint2 u; } cv;
            cv.h.a = __floats2bfloat162_rn(st[m * 129 + n],       st[(m + 1) * 129 + n]);
            cv.h.b = __floats2bfloat162_rn(st[(m + 2) * 129 + n], st[(m + 3) * 129 + n]);
            *(uint2*)&Whz[(size_t)(j0 + n) * NC + i0 + m] = cv.u;
        }
    }
}

// =====================================================================
// Kernel 1b: combine bf16 split-K halves -> g_Ws (f32). Full-chip.
// =====================================================================
__global__ __launch_bounds__(256)
void combine_kernel() {
    const size_t i = (size_t)blockIdx.x * 256 + threadIdx.x;   // uint4 idx (4M/8)
    const uint4 a = ((const uint4*)g_WhA)[i];
    const uint4 b = ((const uint4*)g_WhB)[i];
    const uint32_t* pa = (const uint32_t*)&a;
    const uint32_t* pb = (const uint32_t*)&b;
    float4 o0, o1;
    float* po = (float*)&o0;
    #pragma unroll
    for (int k = 0; k < 4; k++) {
        po[2 * k]     = bflo(pa[k]) + bflo(pb[k]);
        po[2 * k + 1] = bfhi(pa[k]) + bfhi(pb[k]);
    }
    ((float4*)g_Ws)[2 * i]     = o0;
    ((float4*)g_Ws)[2 * i + 1] = o1;
}

// =====================================================================
// Kernel 2: 10 power iterations on f32 Ws, NO per-iteration norm.
// Normalization is a scalar scale; direction == Ws^10 v0 regardless, so
// scale by 2^-13 per iter (lambda_max ~7500 -> norm drifts ~0.92^k, no
// overflow) and normalize exactly ONCE after the loop.
// One block/batch, 1024 thr, 8-way d-split, float4 loads (no unpack ALU).
// <- ncu capture slot this round.
// =====================================================================
__global__ __launch_bounds__(1024)
void power_kernel(const float* __restrict__ vin) {
    const int b = blockIdx.x, t = threadIdx.x;
    const int h = t >> 7;        // d-chunk 0..7 (64 d each)
    const int cg = t & 127;      // c-group: c = 4*cg
    __shared__ float vs[NC];
    __shared__ float part[8 * NC];
    __shared__ float red[16];
    __shared__ float tot;

    if (t < NC) vs[t] = vin[b * NC + t];
    __syncthreads();

    const float4* __restrict__ base =
        (const float4*)(g_Ws + (size_t)b * NC * NC + (size_t)(h * 64) * NC) + cg;

    for (int it = 0; it < NIP; it++) {
        float a0 = 0.f, a1 = 0.f, a2 = 0.f, a3 = 0.f;
        #pragma unroll 16
        for (int d = 0; d < 64; d++) {
            const float4 w = base[(size_t)d * (NC / 4)];
            const float vv = vs[h * 64 + d];
            a0 += vv * w.x; a1 += vv * w.y; a2 += vv * w.z; a3 += vv * w.w;
        }
        *(float4*)&part[h * NC + cg * 4] = make_float4(a0, a1, a2, a3);
        __syncthreads();
        if (t < NC) {
            float nv = 0.f;
            #pragma unroll
            for (int hh = 0; hh < 8; hh++) nv += part[hh * NC + t];
            vs[t] = nv * 0.0001220703125f;   // 2^-13
        }
        __syncthreads();
    }

    // one exact normalization
    float s = 0.f;
    if (t < NC) { const float v = vs[t]; s = v * v; }
    #pragma unroll
    for (int o = 16; o > 0; o >>= 1)
        s += __shfl_xor_sync(0xffffffffu, s, o);
    if (t < NC && (t & 31) == 0) red[t >> 5] = s;
    __syncthreads();
    if (t == 0) {
        float x = 0.f;
        #pragma unroll
        for (int i = 0; i < 16; i++) x += red[i];
        tot = x;
    }
    __syncthreads();
    if (t < NC) g_v[b * NC + t] = vs[t] * rsqrtf(tot);
}

// =====================================================================
// Kernel 3: u partials from bf16 X. grid (4, 16, 16), 256 thr,
// each thread 4 n via uint2 (4 bf16), 32 c.
// =====================================================================
__global__ __launch_bounds__(256)
void u_part_kernel() {
    const int b = blockIdx.z, ch = blockIdx.y;
    const int n0 = blockIdx.x * 1024 + threadIdx.x * 4;
    __shared__ float vsh[32];
    if (threadIdx.x < 32) vsh[threadIdx.x] = g_v[b * NC + ch * 32 + threadIdx.x];
    __syncthreads();

    const __nv_bfloat16* __restrict__ Xp = g_xh + (size_t)b * NC * NHW + (size_t)(ch * 32) * NHW;
    float a0 = 0.f, a1 = 0.f, a2 = 0.f, a3 = 0.f;
    #pragma unroll
    for (int cc = 0; cc < 32; cc++) {
        const uint2 p = *(const uint2*)&Xp[(size_t)cc * NHW + n0];
        const float vv = vsh[cc];
        a0 += vv * bflo(p.x); a1 += vv * bfhi(p.x);
        a2 += vv * bflo(p.y); a3 += vv * bfhi(p.y);
    }
    *(float4*)&g_upar[(size_t)(b * 16 + ch) * NHW + n0] = make_float4(a0, a1, a2, a3);
}

// =====================================================================
// Kernel 4: reduce c-chunk partials -> g_u, compute 1/||u||. grid 16, 512 thr.
// =====================================================================
__global__ __launch_bounds__(512)
void u_reduce_kernel() {
    const int b = blockIdx.x, t = threadIdx.x;
    __shared__ float red[16];
    float sq = 0.f;
    #pragma unroll
    for (int j = 0; j < 8; j++) {
        const int n = j * 512 + t;
        float s = 0.f;
        #pragma unroll
        for (int ch = 0; ch < 16; ch++)
            s += g_upar[(size_t)(b * 16 + ch) * NHW + n];
        g_u[b * NHW + n] = s;
        sq += s * s;
    }
    #pragma unroll
    for (int o = 16; o > 0; o >>= 1)
        sq += __shfl_xor_sync(0xffffffffu, sq, o);
    if ((t & 31) == 0) red[t >> 5] = sq;
    __syncthreads();
    if (t == 0) {
        float x = 0.f;
        #pragma unroll
        for (int i = 0; i < 16; i++) x += red[i];
        g_uinv[b] = rsqrtf(x);
    }
}

// =====================================================================
// Kernel 5: out = x + (v * 1/||u||) outer u. float4 streaming (f32 x).
// =====================================================================
__global__ __launch_bounds__(256)
void final_kernel(const float* __restrict__ x, float* __restrict__ out) {
    const size_t i = (size_t)blockIdx.x * 256 + threadIdx.x;   // float4 idx
    const size_t e = i * 4;
    const int b   = (int)(e >> 21);                 // NC*NHW = 2^21
    const int rem = (int)(e & ((1u << 21) - 1));
    const int c   = rem >> 12;                      // NHW = 2^12
    const int n   = rem & (NHW - 1);
    const float vc = g_v[b * NC + c] * g_uinv[b];
    const float4 u4 = *(const float4*)&g_u[b * NHW + n];
    const float4 xv = *(const float4*)&x[e];
    float4 o;
    o.x = xv.x + vc * u4.x;
    o.y = xv.y + vc * u4.y;
    o.z = xv.z + vc * u4.z;
    o.w = xv.w + vc * u4.w;
    *(float4*)&out[e] = o;
}

// =====================================================================
extern "C" void kernel_launch(void* const* d_in, const int* in_sizes, int n_in,
                              void* d_out, int out_size) {
    const float* x  = (const float*)d_in[0];
    const float* v0 = (const float*)d_in[1];
    float* out = (float*)d_out;

    cudaFuncSetAttribute(gram_mma, cudaFuncAttributeMaxDynamicSharedMemorySize, GRAM_SMEM);

    conv_kernel<<<32768, 256>>>(x);                    // launch 1
    gram_mma<<<dim3(20, NB, 2), 256, GRAM_SMEM>>>();   // launch 2
    combine_kernel<<<2048, 256>>>();                   // launch 3
    power_kernel<<<NB, 1024>>>(v0);                    // launch 4 <- ncu capture slot
    u_part_kernel<<<dim3(4, 16, NB), 256>>>();
    u_reduce_kernel<<<NB, 512>>>();
    final_kernel<<<32768, 256>>>(x, out);
}

// round 16
// speedup vs baseline: 1.1066x; 1.1066x over previous
#include <cuda_runtime.h>
#include <cuda_bf16.h>
#include <cstdint>

#define NB  16
#define NC  512
#define NHW 4096
#define NIP 10

// ---------------- scratch (static device globals; no allocations) ----------------
__device__ __align__(16) __nv_bfloat16 g_xh[NB*NC*NHW];    // bf16 copy of x (64MB)
__device__ __align__(16) __nv_bfloat16 g_WhA[NB*NC*NC];    // split-K half 0, bf16 (8MB)
__device__ __align__(16) __nv_bfloat16 g_WhB[NB*NC*NC];    // split-K half 1, bf16 (8MB)
__device__ __align__(16) __nv_bfloat16 g_Wsh[NB*NC*NC];    // Gram bf16 (8MB)
__device__ float g_v  [NB*NC];        // v after 10 power iterations (unit)
__device__ float g_u  [NB*NHW];       // unnormalized u = X^T v
__device__ float g_upar[NB*16*NHW];   // c-chunk partials of u (4MB)
__device__ float g_uinv [NB];         // 1/||u||

// ================= PTX helpers =================
__device__ __forceinline__ uint32_t smem_u32(const void* p) {
    uint32_t a;
    asm("{ .reg .u64 t; cvta.to.shared.u64 t, %1; cvt.u32.u64 %0, t; }" : "=r"(a) : "l"(p));
    return a;
}
__device__ __forceinline__ void cp16(uint32_t dst, const void* gsrc) {
    asm volatile("cp.async.cg.shared.global [%0], [%1], 16;"
                 :: "r"(dst), "l"(__cvta_generic_to_global(gsrc)) : "memory");
}
#define CP_COMMIT() asm volatile("cp.async.commit_group;" ::: "memory")

__device__ __forceinline__ void ldsm4(uint32_t* r, uint32_t addr) {
    asm volatile("ldmatrix.sync.aligned.m8n8.x4.shared.b16 {%0,%1,%2,%3}, [%4];"
        : "=r"(r[0]), "=r"(r[1]), "=r"(r[2]), "=r"(r[3]) : "r"(addr));
}
__device__ __forceinline__ void mma16816(float* d, const uint32_t* a, uint32_t b0, uint32_t b1) {
    asm volatile("mma.sync.aligned.m16n8k16.row.col.f32.bf16.bf16.f32 "
        "{%0,%1,%2,%3}, {%4,%5,%6,%7}, {%8,%9}, {%0,%1,%2,%3};"
        : "+f"(d[0]), "+f"(d[1]), "+f"(d[2]), "+f"(d[3])
        : "r"(a[0]), "r"(a[1]), "r"(a[2]), "r"(a[3]), "r"(b0), "r"(b1));
}
__device__ __forceinline__ float bflo(uint32_t p) { return __uint_as_float(p << 16); }
__device__ __forceinline__ float bfhi(uint32_t p) { return __uint_as_float(p & 0xffff0000u); }

// =====================================================================
// Kernel 0: convert x (f32) -> g_xh (bf16). Single launch.
// =====================================================================
__global__ __launch_bounds__(256)
void conv_kernel(const float* __restrict__ x) {
    const size_t i = (size_t)blockIdx.x * 256 + threadIdx.x;  // float4 idx
    const float4 v = ((const float4*)x)[i];
    union { struct { __nv_bfloat162 a, b; } h; uint2 u; } cv;
    cv.h.a = __floats2bfloat162_rn(v.x, v.y);
    cv.h.b = __floats2bfloat162_rn(v.z, v.w);
    ((uint2*)g_xh)[i] = cv.u;
}

// =====================================================================
// Kernel 1: Gram via bf16 mma.sync (R13-proven core). CTA tile 64x128,
// 256 thr = 8 warps (2m x 4n of 32x32), __launch_bounds__(256,3).
// Symmetric decomposition (mi in 0..7, nj in 0..3): tiles with mi >= 2nj.
// Straddle tiles alias A into B smem. Split-K=2, BK=32, 4-stage cp.async,
// prefetch +2, one barrier per chunk. Epilogue writes bf16 halves.
// =====================================================================
#define BK 32
#define A_BYTES (64 * 80)             // 5120
#define B_BYTES (128 * 80)            // 10240
#define STAGE_BYTES (A_BYTES + B_BYTES)  // 15360
#define GRAM_SMEM (4 * STAGE_BYTES)   // 61440 >= epilogue 64*129*4 (33024)

__global__ __launch_bounds__(256, 3)
void gram_mma(void) {
    extern __shared__ char ds[];
    const uint32_t sb = smem_u32(ds);
    const int tid = threadIdx.x;
    const int wid = tid >> 5, lane = tid & 31;

    const int b = blockIdx.y;
    const int z = blockIdx.z;            // split-K half
    int nj = 0, r = blockIdx.x;
    while (r >= 8 - 2 * nj) { r -= 8 - 2 * nj; nj++; }
    const int mi = 2 * nj + r;
    const int i0 = mi * 64, j0 = nj * 128;
    const bool straddle = (mi == 2 * nj) || (mi == 2 * nj + 1);
    const bool dotrans  = (mi >= 2 * nj + 2);
    const int kbase = z * 2048;

    const __nv_bfloat16* __restrict__ Xb = g_xh + (size_t)b * NC * NHW;
    __nv_bfloat16* __restrict__ Whz = (z ? g_WhB : g_WhA) + (size_t)b * NC * NC;

    // loader: B = 2 cp16/thread (128 rows x 4 qcols), A = 1 cp16/thread (64 x 4)
    const int br0 = tid >> 2,          bq0 = tid & 3;
    const int br1 = (tid + 256) >> 2,  bq1 = tid & 3;
    const int arow = tid >> 2,         akq = tid & 3;

    auto load_chunk = [&](int c) {
        const uint32_t stg = sb + (uint32_t)(c & 3) * STAGE_BYTES;
        const uint32_t bbs = stg + A_BYTES;
        const __nv_bfloat16* gB = Xb + (size_t)j0 * NHW + kbase + c * BK;
        cp16(bbs + br0 * 80 + bq0 * 16, gB + (size_t)br0 * NHW + bq0 * 8);
        cp16(bbs + br1 * 80 + bq1 * 16, gB + (size_t)br1 * NHW + bq1 * 8);
        if (!straddle) {
            const __nv_bfloat16* gA = Xb + (size_t)i0 * NHW + kbase + c * BK;
            cp16(stg + arow * 80 + akq * 16, gA + (size_t)arow * NHW + akq * 8);
        }
        CP_COMMIT();
    };

    load_chunk(0); load_chunk(1);

    // per-lane ldmatrix address offsets (bytes) — verified R5..R14
    const uint32_t aoff = (uint32_t)((lane & 15) * 80 + (lane >> 4) * 16);
    const uint32_t boff = (uint32_t)(((lane & 7) | (((lane >> 4) & 1) << 3)) * 80
                                     + ((lane >> 3) & 1) * 16);
    const uint32_t wmB = (uint32_t)((wid & 1) * 32) * 80;   // warp m0 byte off
    const uint32_t wnB = (uint32_t)((wid >> 1) * 32) * 80;  // warp n0 byte off
    const uint32_t astrad = (uint32_t)(mi & 1) * 5120u;     // A offset inside B tile

    float acc[2][4][4];
    #pragma unroll
    for (int mt = 0; mt < 2; mt++)
        #pragma unroll
        for (int nt = 0; nt < 4; nt++)
            #pragma unroll
            for (int q = 0; q < 4; q++) acc[mt][nt][q] = 0.f;

    for (int c = 0; c < 64; c++) {
        if (c < 63) asm volatile("cp.async.wait_group 1;" ::: "memory");
        else        asm volatile("cp.async.wait_group 0;" ::: "memory");
        __syncthreads();     // chunk c resident; stage (c+2)%4 reads (chunk c-2) done

        if (c + 2 < 64) load_chunk(c + 2);

        const uint32_t stg = sb + (uint32_t)(c & 3) * STAGE_BYTES;
        const uint32_t bbs = stg + A_BYTES;
        const uint32_t abs_ = straddle ? (bbs + astrad) : stg;

        #pragma unroll
        for (int ks = 0; ks < 2; ks++) {
            uint32_t af[2][4], bf[2][4];
            #pragma unroll
            for (int mt = 0; mt < 2; mt++)
                ldsm4(af[mt], abs_ + wmB + (uint32_t)(mt * 1280 + ks * 32) + aoff);
            #pragma unroll
            for (int nh = 0; nh < 2; nh++)
                ldsm4(bf[nh], bbs + wnB + (uint32_t)(nh * 1280 + ks * 32) + boff);
            #pragma unroll
            for (int mt = 0; mt < 2; mt++)
                #pragma unroll
                for (int nt = 0; nt < 4; nt++)
                    mma16816(acc[mt][nt], af[mt], bf[nt >> 1][2 * (nt & 1)],
                             bf[nt >> 1][2 * (nt & 1) + 1]);
        }
    }
    __syncthreads();   // all MMA reads done before smem reuse

    // ---- epilogue: stage 64x128 C in smem (stride 129 floats) ----
    float* st = (float*)ds;
    {
        const int gid = lane >> 2, tig = lane & 3;
        const int wm0 = (wid & 1) * 32, wn0 = (wid >> 1) * 32;
        #pragma unroll
        for (int mt = 0; mt < 2; mt++)
            #pragma unroll
            for (int nt = 0; nt < 4; nt++) {
                const int m = wm0 + mt * 16 + gid;
                const int n = wn0 + nt * 8 + tig * 2;
                st[m * 129 + n]           = acc[mt][nt][0];
                st[m * 129 + n + 1]       = acc[mt][nt][1];
                st[(m + 8) * 129 + n]     = acc[mt][nt][2];
                st[(m + 8) * 129 + n + 1] = acc[mt][nt][3];
            }
    }
    __syncthreads();

    // direct block (i0, j0): 64 x 128, bf16
    #pragma unroll
    for (int it = 0; it < 8; it++) {
        const int e = it * 256 + tid;        // 2048 uint2 (4 cols each)
        const int row = e >> 5, n = (e & 31) * 4;
        union { struct { __nv_bfloat162 a, b; } h; uint2 u; } cv;
        cv.h.a = __floats2bfloat162_rn(st[row * 129 + n],     st[row * 129 + n + 1]);
        cv.h.b = __floats2bfloat162_rn(st[row * 129 + n + 2], st[row * 129 + n + 3]);
        *(uint2*)&Whz[(size_t)(i0 + row) * NC + j0 + n] = cv.u;
    }
    // transposed block (j0, i0): 128 x 64, bf16
    if (dotrans) {
        #pragma unroll
        for (int it = 0; it < 8; it++) {
            const int e = it * 256 + tid;    // 2048 uint2
            const int n = e >> 4, m = (e & 15) * 4;
            union { struct { __nv_bfloat162 a, b; } h; uint2 u; } cv;
            cv.h.a = __floats2bfloat162_rn(st[m * 129 + n],       st[(m + 1) * 129 + n]);
            cv.h.b = __floats2bfloat162_rn(st[(m + 2) * 129 + n], st[(m + 3) * 129 + n]);
            *(uint2*)&Whz[(size_t)(j0 + n) * NC + i0 + m] = cv.u;
        }
    }
}

// =====================================================================
// Kernel 1b: combine bf16 split-K halves -> g_Wsh (bf16, __hadd2).
// R14-proven version (the R15 f32 rewrite had uninitialized-var UB).
// =====================================================================
__global__ __launch_bounds__(256)
void combine_kernel() {
    const size_t i = (size_t)blockIdx.x * 256 + threadIdx.x;   // uint4 idx (4M/8)
    const uint4 a = ((const uint4*)g_WhA)[i];
    const uint4 b = ((const uint4*)g_WhB)[i];
    uint4 o;
    const __nv_bfloat162* pa = (const __nv_bfloat162*)&a;
    const __nv_bfloat162* pb = (const __nv_bfloat162*)&b;
    __nv_bfloat162* po = (__nv_bfloat162*)&o;
    #pragma unroll
    for (int k = 0; k < 4; k++) po[k] = __hadd2(pa[k], pb[k]);
    ((uint4*)g_Wsh)[i] = o;
}

// =====================================================================
// Kernel 2: 10 power iterations on bf16 Ws, NO per-iteration norm.
// Per-iter scale 2^-13 is an exact power of two -> direction identical
// to the normalized iteration; one exact normalization after the loop.
// One block/batch, 1024 thr, 8-way d-split, uint2 bf16 loads (R14 path).
// 2 barriers/iter (was 4) and no per-iter shuffle tree / serial sum.
// <- ncu capture slot this round.
// =====================================================================
__global__ __launch_bounds__(1024)
void power_kernel(const float* __restrict__ vin) {
    const int b = blockIdx.x, t = threadIdx.x;
    const int h = t >> 7;        // d-chunk 0..7 (64 d each)
    const int cg = t & 127;      // c-group: c = 4*cg
    __shared__ float vs[NC];
    __shared__ float part[8 * NC];
    __shared__ float red[16];
    __shared__ float tot;

    if (t < NC) vs[t] = vin[b * NC + t];
    __syncthreads();

    const uint2* __restrict__ base =
        (const uint2*)(g_Wsh + (size_t)b * NC * NC + (size_t)(h * 64) * NC) + cg;

    for (int it = 0; it < NIP; it++) {
        float a0 = 0.f, a1 = 0.f, a2 = 0.f, a3 = 0.f;
        #pragma unroll 16
        for (int d = 0; d < 64; d++) {
            const uint2 p = base[(size_t)d * (NC / 4)];
            const float vv = vs[h * 64 + d];
            a0 += vv * bflo(p.x); a1 += vv * bfhi(p.x);
            a2 += vv * bflo(p.y); a3 += vv * bfhi(p.y);
        }
        *(float4*)&part[h * NC + cg * 4] = make_float4(a0, a1, a2, a3);
        __syncthreads();                    // matvec reads of vs done; parts visible
        if (t < NC) {
            float nv = 0.f;
            #pragma unroll
            for (int hh = 0; hh < 8; hh++) nv += part[hh * NC + t];
            vs[t] = nv * 0.0001220703125f;  // 2^-13 (exact)
        }
        __syncthreads();
    }

    // one exact normalization
    float s = 0.f;
    if (t < NC) { const float v = vs[t]; s = v * v; }
    #pragma unroll
    for (int o = 16; o > 0; o >>= 1)
        s += __shfl_xor_sync(0xffffffffu, s, o);
    if (t < NC && (t & 31) == 0) red[t >> 5] = s;
    __syncthreads();
    if (t == 0) {
        float x = 0.f;
        #pragma unroll
        for (int i = 0; i < 16; i++) x += red[i];
        tot = x;
    }
    __syncthreads();
    if (t < NC) g_v[b * NC + t] = vs[t] * rsqrtf(tot);
}

// =====================================================================
// Kernel 3: u partials from bf16 X. grid (4, 16, 16), 256 thr,
// each thread 4 n via uint2 (4 bf16), 32 c.
// =====================================================================
__global__ __launch_bounds__(256)
void u_part_kernel() {
    const int b = blockIdx.z, ch = blockIdx.y;
    const int n0 = blockIdx.x * 1024 + threadIdx.x * 4;
    __shared__ float vsh[32];
    if (threadIdx.x < 32) vsh[threadIdx.x] = g_v[b * NC + ch * 32 + threadIdx.x];
    __syncthreads();

    const __nv_bfloat16* __restrict__ Xp = g_xh + (size_t)b * NC * NHW + (size_t)(ch * 32) * NHW;
    float a0 = 0.f, a1 = 0.f, a2 = 0.f, a3 = 0.f;
    #pragma unroll
    for (int cc = 0; cc < 32; cc++) {
        const uint2 p = *(const uint2*)&Xp[(size_t)cc * NHW + n0];
        const float vv = vsh[cc];
        a0 += vv * bflo(p.x); a1 += vv * bfhi(p.x);
        a2 += vv * bflo(p.y); a3 += vv * bfhi(p.y);
    }
    *(float4*)&g_upar[(size_t)(b * 16 + ch) * NHW + n0] = make_float4(a0, a1, a2, a3);
}

// =====================================================================
// Kernel 4: reduce c-chunk partials -> g_u, compute 1/||u||. grid 16, 512 thr.
// =====================================================================
__global__ __launch_bounds__(512)
void u_reduce_kernel() {
    const int b = blockIdx.x, t = threadIdx.x;
    __shared__ float red[16];
    float sq = 0.f;
    #pragma unroll
    for (int j = 0; j < 8; j++) {
        const int n = j * 512 + t;
        float s = 0.f;
        #pragma unroll
        for (int ch = 0; ch < 16; ch++)
            s += g_upar[(size_t)(b * 16 + ch) * NHW + n];
        g_u[b * NHW + n] = s;
        sq += s * s;
    }
    #pragma unroll
    for (int o = 16; o > 0; o >>= 1)
        sq += __shfl_xor_sync(0xffffffffu, sq, o);
    if ((t & 31) == 0) red[t >> 5] = sq;
    __syncthreads();
    if (t == 0) {
        float x = 0.f;
        #pragma unroll
        for (int i = 0; i < 16; i++) x += red[i];
        g_uinv[b] = rsqrtf(x);
    }
}

// =====================================================================
// Kernel 5: out = x + (v * 1/||u||) outer u. float4 streaming (f32 x).
// =====================================================================
__global__ __launch_bounds__(256)
void final_kernel(const float* __restrict__ x, float* __restrict__ out) {
    const size_t i = (size_t)blockIdx.x * 256 + threadIdx.x;   // float4 idx
    const size_t e = i * 4;
    const int b   = (int)(e >> 21);                 // NC*NHW = 2^21
    const int rem = (int)(e & ((1u << 21) - 1));
    const int c   = rem >> 12;                      // NHW = 2^12
    const int n   = rem & (NHW - 1);
    const float vc = g_v[b * NC + c] * g_uinv[b];
    const float4 u4 = *(const float4*)&g_u[b * NHW + n];
    const float4 xv = *(const float4*)&x[e];
    float4 o;
    o.x = xv.x + vc * u4.x;
    o.y = xv.y + vc * u4.y;
    o.z = xv.z + vc * u4.z;
    o.w = xv.w + vc * u4.w;
    *(float4*)&out[e] = o;
}

// =====================================================================
extern "C" void kernel_launch(void* const* d_in, const int* in_sizes, int n_in,
                              void* d_out, int out_size) {
    const float* x  = (const float*)d_in[0];
    const float* v0 = (const float*)d_in[1];
    float* out = (float*)d_out;

    cudaFuncSetAttribute(gram_mma, cudaFuncAttributeMaxDynamicSharedMemorySize, GRAM_SMEM);

    conv_kernel<<<32768, 256>>>(x);                    // launch 1
    gram_mma<<<dim3(20, NB, 2), 256, GRAM_SMEM>>>();   // launch 2
    combine_kernel<<<2048, 256>>>();                   // launch 3
    power_kernel<<<NB, 1024>>>(v0);                    // launch 4 <- ncu capture slot
    u_part_kernel<<<dim3(4, 16, NB), 256>>>();
    u_reduce_kernel<<<NB, 512>>>();
    final_kernel<<<32768, 256>>>(x, out);
}

// round 17
// speedup vs baseline: 1.1200x; 1.0121x over previous
#include <cuda_runtime.h>
#include <cuda_bf16.h>
#include <cstdint>

#define NB  16
#define NC  512
#define NHW 4096
#define NIP 10

// ---------------- scratch (static device globals; no allocations) ----------------
__device__ __align__(16) __nv_bfloat16 g_xh[NB*NC*NHW];    // bf16 copy of x (64MB)
__device__ __align__(16) __nv_bfloat16 g_WhA[NB*NC*NC];    // split-K half 0, bf16 (8MB)
__device__ __align__(16) __nv_bfloat16 g_WhB[NB*NC*NC];    // split-K half 1, bf16 (8MB)
__device__ __align__(16) __nv_bfloat16 g_Wsh[NB*NC*NC];    // Gram bf16 (8MB)
__device__ float g_v  [NB*NC];        // v after 10 power iterations (unit)
__device__ float g_u  [NB*NHW];       // unnormalized u = X^T v
__device__ float g_upar[NB*16*NHW];   // c-chunk partials of u (4MB)
__device__ float g_uinv [NB];         // 1/||u||
__device__ float g_vtmp[2][NB*NC];    // parity-buffered v halves for inter-CTA exchange
__device__ int   g_sync[NB];          // per-batch arrival counters (reset in combine)

// ================= PTX helpers =================
__device__ __forceinline__ uint32_t smem_u32(const void* p) {
    uint32_t a;
    asm("{ .reg .u64 t; cvta.to.shared.u64 t, %1; cvt.u32.u64 %0, t; }" : "=r"(a) : "l"(p));
    return a;
}
__device__ __forceinline__ void cp16(uint32_t dst, const void* gsrc) {
    asm volatile("cp.async.cg.shared.global [%0], [%1], 16;"
                 :: "r"(dst), "l"(__cvta_generic_to_global(gsrc)) : "memory");
}
#define CP_COMMIT() asm volatile("cp.async.commit_group;" ::: "memory")

__device__ __forceinline__ void ldsm4(uint32_t* r, uint32_t addr) {
    asm volatile("ldmatrix.sync.aligned.m8n8.x4.shared.b16 {%0,%1,%2,%3}, [%4];"
        : "=r"(r[0]), "=r"(r[1]), "=r"(r[2]), "=r"(r[3]) : "r"(addr));
}
__device__ __forceinline__ void mma16816(float* d, const uint32_t* a, uint32_t b0, uint32_t b1) {
    asm volatile("mma.sync.aligned.m16n8k16.row.col.f32.bf16.bf16.f32 "
        "{%0,%1,%2,%3}, {%4,%5,%6,%7}, {%8,%9}, {%0,%1,%2,%3};"
        : "+f"(d[0]), "+f"(d[1]), "+f"(d[2]), "+f"(d[3])
        : "r"(a[0]), "r"(a[1]), "r"(a[2]), "r"(a[3]), "r"(b0), "r"(b1));
}
__device__ __forceinline__ float bflo(uint32_t p) { return __uint_as_float(p << 16); }
__device__ __forceinline__ float bfhi(uint32_t p) { return __uint_as_float(p & 0xffff0000u); }

// =====================================================================
// Kernel 0: convert x (f32) -> g_xh (bf16). Single launch.
// =====================================================================
__global__ __launch_bounds__(256)
void conv_kernel(const float* __restrict__ x) {
    const size_t i = (size_t)blockIdx.x * 256 + threadIdx.x;  // float4 idx
    const float4 v = ((const float4*)x)[i];
    union { struct { __nv_bfloat162 a, b; } h; uint2 u; } cv;
    cv.h.a = __floats2bfloat162_rn(v.x, v.y);
    cv.h.b = __floats2bfloat162_rn(v.z, v.w);
    ((uint2*)g_xh)[i] = cv.u;
}

// =====================================================================
// Kernel 1: Gram via bf16 mma.sync (R13-proven core). CTA tile 64x128,
// 256 thr = 8 warps (2m x 4n of 32x32), __launch_bounds__(256,3).
// Symmetric decomposition (mi in 0..7, nj in 0..3): tiles with mi >= 2nj.
// Straddle tiles alias A into B smem. Split-K=2, BK=32, 4-stage cp.async,
// prefetch +2, one barrier per chunk. Epilogue writes bf16 halves.
// =====================================================================
#define BK 32
#define A_BYTES (64 * 80)             // 5120
#define B_BYTES (128 * 80)            // 10240
#define STAGE_BYTES (A_BYTES + B_BYTES)  // 15360
#define GRAM_SMEM (4 * STAGE_BYTES)   // 61440 >= epilogue 64*129*4 (33024)

__global__ __launch_bounds__(256, 3)
void gram_mma(void) {
    extern __shared__ char ds[];
    const uint32_t sb = smem_u32(ds);
    const int tid = threadIdx.x;
    const int wid = tid >> 5, lane = tid & 31;

    const int b = blockIdx.y;
    const int z = blockIdx.z;            // split-K half
    int nj = 0, r = blockIdx.x;
    while (r >= 8 - 2 * nj) { r -= 8 - 2 * nj; nj++; }
    const int mi = 2 * nj + r;
    const int i0 = mi * 64, j0 = nj * 128;
    const bool straddle = (mi == 2 * nj) || (mi == 2 * nj + 1);
    const bool dotrans  = (mi >= 2 * nj + 2);
    const int kbase = z * 2048;

    const __nv_bfloat16* __restrict__ Xb = g_xh + (size_t)b * NC * NHW;
    __nv_bfloat16* __restrict__ Whz = (z ? g_WhB : g_WhA) + (size_t)b * NC * NC;

    // loader: B = 2 cp16/thread (128 rows x 4 qcols), A = 1 cp16/thread (64 x 4)
    const int br0 = tid >> 2,          bq0 = tid & 3;
    const int br1 = (tid + 256) >> 2,  bq1 = tid & 3;
    const int arow = tid >> 2,         akq = tid & 3;

    auto load_chunk = [&](int c) {
        const uint32_t stg = sb + (uint32_t)(c & 3) * STAGE_BYTES;
        const uint32_t bbs = stg + A_BYTES;
        const __nv_bfloat16* gB = Xb + (size_t)j0 * NHW + kbase + c * BK;
        cp16(bbs + br0 * 80 + bq0 * 16, gB + (size_t)br0 * NHW + bq0 * 8);
        cp16(bbs + br1 * 80 + bq1 * 16, gB + (size_t)br1 * NHW + bq1 * 8);
        if (!straddle) {
            const __nv_bfloat16* gA = Xb + (size_t)i0 * NHW + kbase + c * BK;
            cp16(stg + arow * 80 + akq * 16, gA + (size_t)arow * NHW + akq * 8);
        }
        CP_COMMIT();
    };

    load_chunk(0); load_chunk(1);

    // per-lane ldmatrix address offsets (bytes) — verified R5..R16
    const uint32_t aoff = (uint32_t)((lane & 15) * 80 + (lane >> 4) * 16);
    const uint32_t boff = (uint32_t)(((lane & 7) | (((lane >> 4) & 1) << 3)) * 80
                                     + ((lane >> 3) & 1) * 16);
    const uint32_t wmB = (uint32_t)((wid & 1) * 32) * 80;   // warp m0 byte off
    const uint32_t wnB = (uint32_t)((wid >> 1) * 32) * 80;  // warp n0 byte off
    const uint32_t astrad = (uint32_t)(mi & 1) * 5120u;     // A offset inside B tile

    float acc[2][4][4];
    #pragma unroll
    for (int mt = 0; mt < 2; mt++)
        #pragma unroll
        for (int nt = 0; nt < 4; nt++)
            #pragma unroll
            for (int q = 0; q < 4; q++) acc[mt][nt][q] = 0.f;

    for (int c = 0; c < 64; c++) {
        if (c < 63) asm volatile("cp.async.wait_group 1;" ::: "memory");
        else        asm volatile("cp.async.wait_group 0;" ::: "memory");
        __syncthreads();     // chunk c resident; stage (c+2)%4 reads (chunk c-2) done

        if (c + 2 < 64) load_chunk(c + 2);

        const uint32_t stg = sb + (uint32_t)(c & 3) * STAGE_BYTES;
        const uint32_t bbs = stg + A_BYTES;
        const uint32_t abs_ = straddle ? (bbs + astrad) : stg;

        #pragma unroll
        for (int ks = 0; ks < 2; ks++) {
            uint32_t af[2][4], bf[2][4];
            #pragma unroll
            for (int mt = 0; mt < 2; mt++)
                ldsm4(af[mt], abs_ + wmB + (uint32_t)(mt * 1280 + ks * 32) + aoff);
            #pragma unroll
            for (int nh = 0; nh < 2; nh++)
                ldsm4(bf[nh], bbs + wnB + (uint32_t)(nh * 1280 + ks * 32) + boff);
            #pragma unroll
            for (int mt = 0; mt < 2; mt++)
                #pragma unroll
                for (int nt = 0; nt < 4; nt++)
                    mma16816(acc[mt][nt], af[mt], bf[nt >> 1][2 * (nt & 1)],
                             bf[nt >> 1][2 * (nt & 1) + 1]);
        }
    }
    __syncthreads();   // all MMA reads done before smem reuse

    // ---- epilogue: stage 64x128 C in smem (stride 129 floats) ----
    float* st = (float*)ds;
    {
        const int gid = lane >> 2, tig = lane & 3;
        const int wm0 = (wid & 1) * 32, wn0 = (wid >> 1) * 32;
        #pragma unroll
        for (int mt = 0; mt < 2; mt++)
            #pragma unroll
            for (int nt = 0; nt < 4; nt++) {
                const int m = wm0 + mt * 16 + gid;
                const int n = wn0 + nt * 8 + tig * 2;
                st[m * 129 + n]           = acc[mt][nt][0];
                st[m * 129 + n + 1]       = acc[mt][nt][1];
                st[(m + 8) * 129 + n]     = acc[mt][nt][2];
                st[(m + 8) * 129 + n + 1] = acc[mt][nt][3];
            }
    }
    __syncthreads();

    // direct block (i0, j0): 64 x 128, bf16
    #pragma unroll
    for (int it = 0; it < 8; it++) {
        const int e = it * 256 + tid;        // 2048 uint2 (4 cols each)
        const int row = e >> 5, n = (e & 31) * 4;
        union { struct { __nv_bfloat162 a, b; } h; uint2 u; } cv;
        cv.h.a = __floats2bfloat162_rn(st[row * 129 + n],     st[row * 129 + n + 1]);
        cv.h.b = __floats2bfloat162_rn(st[row * 129 + n + 2], st[row * 129 + n + 3]);
        *(uint2*)&Whz[(size_t)(i0 + row) * NC + j0 + n] = cv.u;
    }
    // transposed block (j0, i0): 128 x 64, bf16
    if (dotrans) {
        #pragma unroll
        for (int it = 0; it < 8; it++) {
            const int e = it * 256 + tid;    // 2048 uint2
            const int n = e >> 4, m = (e & 15) * 4;
            union { struct { __nv_bfloat162 a, b; } h; uint2 u; } cv;
            cv.h.a = __floats2bfloat162_rn(st[m * 129 + n],       st[(m + 1) * 129 + n]);
            cv.h.b = __floats2bfloat162_rn(st[(m + 2) * 129 + n], st[(m + 3) * 129 + n]);
            *(uint2*)&Whz[(size_t)(j0 + n) * NC + i0 + m] = cv.u;
        }
    }
}

// =====================================================================
// Kernel 1b: combine bf16 split-K halves -> g_Wsh (bf16, __hadd2).
// Also resets the power-kernel sync counters (runs before power in-stream).
// =====================================================================
__global__ __launch_bounds__(256)
void combine_kernel() {
    if (blockIdx.x == 0 && threadIdx.x < NB) g_sync[threadIdx.x] = 0;
    const size_t i = (size_t)blockIdx.x * 256 + threadIdx.x;   // uint4 idx (4M/8)
    const uint4 a = ((const uint4*)g_WhA)[i];
    const uint4 b = ((const uint4*)g_WhB)[i];
    uint4 o;
    const __nv_bfloat162* pa = (const __nv_bfloat162*)&a;
    const __nv_bfloat162* pb = (const __nv_bfloat162*)&b;
    __nv_bfloat162* po = (__nv_bfloat162*)&o;
    #pragma unroll
    for (int k = 0; k < 4; k++) po[k] = __hadd2(pa[k], pb[k]);
    ((uint4*)g_Wsh)[i] = o;
}

// =====================================================================
// Kernel 2: power iterations, 2 CTAs per batch (grid 32 — all resident,
// no deadlock). Each CTA owns 256 output rows; 16-way d-split over 1024
// threads halves the per-thread issue work vs R16. Halves exchanged via
// parity-double-buffered g_vtmp + per-batch arrival counter (writers
// fence, one thread atomicAdd + spin). No per-iter norm (scale 2^-13,
// exact power of two); one exact normalization at the end (half 0 writes).
// <- ncu capture slot this round.
// =====================================================================
__global__ __launch_bounds__(1024)
void power_kernel(const float* __restrict__ vin) {
    const int b = blockIdx.x >> 1;
    const int half = blockIdx.x & 1;
    const int c0 = half * 256;
    const int t = threadIdx.x;
    const int h = t >> 6;        // d-chunk 0..15 (32 d each)
    const int cg = t & 63;       // c-group within own half: c = c0 + 4*cg
    __shared__ float vs[NC];
    __shared__ float part[16 * 256];
    __shared__ float red[16];
    __shared__ float tot;

    if (t < NC) vs[t] = vin[b * NC + t];
    __syncthreads();

    const uint2* __restrict__ base =
        (const uint2*)(g_Wsh + (size_t)b * NC * NC + (size_t)(h * 32) * NC + c0) + cg;

    for (int it = 0; it < NIP; it++) {
        float a0 = 0.f, a1 = 0.f, a2 = 0.f, a3 = 0.f;
        #pragma unroll 16
        for (int d = 0; d < 32; d++) {
            const uint2 p = base[(size_t)d * (NC / 4)];
            const float vv = vs[h * 32 + d];
            a0 += vv * bflo(p.x); a1 += vv * bfhi(p.x);
            a2 += vv * bflo(p.y); a3 += vv * bfhi(p.y);
        }
        *(float4*)&part[h * 256 + cg * 4] = make_float4(a0, a1, a2, a3);
        __syncthreads();

        if (t < 256) {
            float nv = 0.f;
            #pragma unroll
            for (int hh = 0; hh < 16; hh++) nv += part[hh * 256 + t];
            nv *= 0.0001220703125f;            // 2^-13 (exact)
            vs[c0 + t] = nv;
            g_vtmp[it & 1][b * NC + c0 + t] = nv;
            __threadfence();                   // writer-side release to L2
        }
        __syncthreads();
        if (t == 0) {
            atomicAdd(&g_sync[b], 1);
            while (((volatile int*)g_sync)[b] < 2 * (it + 1)) { }
        }
        __syncthreads();
        // read peer half (volatile -> bypasses L1; writer fenced to L2)
        if (t < 256)
            vs[(c0 ^ 256) + t] = ((volatile float*)g_vtmp[it & 1])[b * NC + (c0 ^ 256) + t];
        __syncthreads();
    }

    // one exact normalization; half 0 writes g_v
    float s = 0.f;
    if (t < NC) { const float v = vs[t]; s = v * v; }
    #pragma unroll
    for (int o = 16; o > 0; o >>= 1)
        s += __shfl_xor_sync(0xffffffffu, s, o);
    if (t < NC && (t & 31) == 0) red[t >> 5] = s;
    __syncthreads();
    if (t == 0) {
        float x = 0.f;
        #pragma unroll
        for (int i = 0; i < 16; i++) x += red[i];
        tot = x;
    }
    __syncthreads();
    if (half == 0 && t < NC) g_v[b * NC + t] = vs[t] * rsqrtf(tot);
}

// =====================================================================
// Kernel 3: u partials from bf16 X. grid (4, 16, 16), 256 thr,
// each thread 4 n via uint2 (4 bf16), 32 c.
// =====================================================================
__global__ __launch_bounds__(256)
void u_part_kernel() {
    const int b = blockIdx.z, ch = blockIdx.y;
    const int n0 = blockIdx.x * 1024 + threadIdx.x * 4;
    __shared__ float vsh[32];
    if (threadIdx.x < 32) vsh[threadIdx.x] = g_v[b * NC + ch * 32 + threadIdx.x];
    __syncthreads();

    const __nv_bfloat16* __restrict__ Xp = g_xh + (size_t)b * NC * NHW + (size_t)(ch * 32) * NHW;
    float a0 = 0.f, a1 = 0.f, a2 = 0.f, a3 = 0.f;
    #pragma unroll
    for (int cc = 0; cc < 32; cc++) {
        const uint2 p = *(const uint2*)&Xp[(size_t)cc * NHW + n0];
        const float vv = vsh[cc];
        a0 += vv * bflo(p.x); a1 += vv * bfhi(p.x);
        a2 += vv * bflo(p.y); a3 += vv * bfhi(p.y);
    }
    *(float4*)&g_upar[(size_t)(b * 16 + ch) * NHW + n0] = make_float4(a0, a1, a2, a3);
}

// =====================================================================
// Kernel 4: reduce c-chunk partials -> g_u, compute 1/||u||. grid 16, 512 thr.
// =====================================================================
__global__ __launch_bounds__(512)
void u_reduce_kernel() {
    const int b = blockIdx.x, t = threadIdx.x;
    __shared__ float red[16];
    float sq = 0.f;
    #pragma unroll
    for (int j = 0; j < 8; j++) {
        const int n = j * 512 + t;
        float s = 0.f;
        #pragma unroll
        for (int ch = 0; ch < 16; ch++)
            s += g_upar[(size_t)(b * 16 + ch) * NHW + n];
        g_u[b * NHW + n] = s;
        sq += s * s;
    }
    #pragma unroll
    for (int o = 16; o > 0; o >>= 1)
        sq += __shfl_xor_sync(0xffffffffu, sq, o);
    if ((t & 31) == 0) red[t >> 5] = sq;
    __syncthreads();
    if (t == 0) {
        float x = 0.f;
        #pragma unroll
        for (int i = 0; i < 16; i++) x += red[i];
        g_uinv[b] = rsqrtf(x);
    }
}

// =====================================================================
// Kernel 5: out = x + (v * 1/||u||) outer u. float4 streaming (f32 x).
// =====================================================================
__global__ __launch_bounds__(256)
void final_kernel(const float* __restrict__ x, float* __restrict__ out) {
    const size_t i = (size_t)blockIdx.x * 256 + threadIdx.x;   // float4 idx
    const size_t e = i * 4;
    const int b   = (int)(e >> 21);                 // NC*NHW = 2^21
    const int rem = (int)(e & ((1u << 21) - 1));
    const int c   = rem >> 12;                      // NHW = 2^12
    const int n   = rem & (NHW - 1);
    const float vc = g_v[b * NC + c] * g_uinv[b];
    const float4 u4 = *(const float4*)&g_u[b * NHW + n];
    const float4 xv = *(const float4*)&x[e];
    float4 o;
    o.x = xv.x + vc * u4.x;
    o.y = xv.y + vc * u4.y;
    o.z = xv.z + vc * u4.z;
    o.w = xv.w + vc * u4.w;
    *(float4*)&out[e] = o;
}

// =====================================================================
extern "C" void kernel_launch(void* const* d_in, const int* in_sizes, int n_in,
                              void* d_out, int out_size) {
    const float* x  = (const float*)d_in[0];
    const float* v0 = (const float*)d_in[1];
    float* out = (float*)d_out;

    cudaFuncSetAttribute(gram_mma, cudaFuncAttributeMaxDynamicSharedMemorySize, GRAM_SMEM);

    conv_kernel<<<32768, 256>>>(x);                    // launch 1
    gram_mma<<<dim3(20, NB, 2), 256, GRAM_SMEM>>>();   // launch 2
    combine_kernel<<<2048, 256>>>();                   // launch 3 (also resets g_sync)
    power_kernel<<<2 * NB, 1024>>>(v0);                // launch 4 <- ncu capture slot
    u_part_kernel<<<dim3(4, 16, NB), 256>>>();
    u_reduce_kernel<<<NB, 512>>>();
    final_kernel<<<32768, 256>>>(x, out);
}